// round 4
// baseline (speedup 1.0000x reference)
#include <cuda_runtime.h>

#define B_  16
#define C_  64
#define N_  512
#define T_  128
#define NT_ (N_ * T_)   // 65536

// Scratch (device globals — no allocation allowed in kernel_launch)
__device__ float g_k[B_ * C_ * T_];     // [16,64,128]  k = einsum('bcit,i->bct')
__device__ float g_att[B_ * C_ * C_];   // [16,64,64]   softmax(k Wc k^T)

// ---------------------------------------------------------------------------
// Kernel 1: k[b,c,t] = sum_n signals[b,c,n,t] * alpha[n]
// One block per (b,c); thread t owns column t; coalesced stride-T loads.
// ---------------------------------------------------------------------------
__global__ void __launch_bounds__(128) k_reduce_kernel(
    const float* __restrict__ sig, const float* __restrict__ alpha)
{
    __shared__ float al[N_];
    const int tid = threadIdx.x;
    #pragma unroll
    for (int i = tid; i < N_; i += 128) al[i] = alpha[i];
    __syncthreads();

    const int bc = blockIdx.x;
    const float* p = sig + (size_t)bc * NT_ + tid;

    float a0 = 0.f, a1 = 0.f, a2 = 0.f, a3 = 0.f;
    #pragma unroll 4
    for (int n = 0; n < N_; n += 4) {
        a0 = fmaf(p[(size_t)(n + 0) * T_], al[n + 0], a0);
        a1 = fmaf(p[(size_t)(n + 1) * T_], al[n + 1], a1);
        a2 = fmaf(p[(size_t)(n + 2) * T_], al[n + 2], a2);
        a3 = fmaf(p[(size_t)(n + 3) * T_], al[n + 3], a3);
    }
    g_k[bc * T_ + tid] = (a0 + a1) + (a2 + a3);
}

// ---------------------------------------------------------------------------
// Kernel 2: scores[b,c,d] = k[b,c,:] @ Wc @ k[b,d,:], softmax over d -> g_att
// One block per batch, 8 warps x 8 rows each. kk padded to 129 floats/row to
// kill bank conflicts on the kk[d*129+s] reads (bank = (lane+s)%32).
// ---------------------------------------------------------------------------
__global__ void __launch_bounds__(256) k_att_kernel(const float* __restrict__ Wc)
{
    __shared__ float kk[C_ * (T_ + 1)];   // 64 x 129
    __shared__ float srow[8][T_ + 4];     // per-warp kW row buffer

    const int b    = blockIdx.x;
    const int tid  = threadIdx.x;
    const int lane = tid & 31;
    const int w    = tid >> 5;

    const float* kb = g_k + b * (C_ * T_);
    for (int i = tid; i < C_ * T_; i += 256) {
        int c = i >> 7, t = i & 127;
        kk[c * (T_ + 1) + t] = kb[i];
    }
    __syncthreads();

    // kW[c,s] = sum_t k[c,t] * Wc[t,s] for this warp's 8 rows, s = lane*4..+3
    float kw[8][4];
    #pragma unroll
    for (int r = 0; r < 8; r++) { kw[r][0] = kw[r][1] = kw[r][2] = kw[r][3] = 0.f; }

    const float4* W4 = (const float4*)Wc;
    for (int t = 0; t < T_; t++) {
        float4 wv = __ldg(&W4[t * 32 + lane]);
        #pragma unroll
        for (int r = 0; r < 8; r++) {
            float kc = kk[(w * 8 + r) * (T_ + 1) + t];
            kw[r][0] = fmaf(kc, wv.x, kw[r][0]);
            kw[r][1] = fmaf(kc, wv.y, kw[r][1]);
            kw[r][2] = fmaf(kc, wv.z, kw[r][2]);
            kw[r][3] = fmaf(kc, wv.w, kw[r][3]);
        }
    }

    float* arow_base = g_att + b * (C_ * C_);
    for (int r = 0; r < 8; r++) {
        const int c = w * 8 + r;
        srow[w][lane * 4 + 0] = kw[r][0];
        srow[w][lane * 4 + 1] = kw[r][1];
        srow[w][lane * 4 + 2] = kw[r][2];
        srow[w][lane * 4 + 3] = kw[r][3];
        __syncwarp();

        // scores[c,d] for d = lane and d = lane+32
        float s0 = 0.f, s1 = 0.f;
        #pragma unroll 4
        for (int s = 0; s < T_; s++) {
            float v = srow[w][s];
            s0 = fmaf(v, kk[lane * (T_ + 1) + s], s0);
            s1 = fmaf(v, kk[(lane + 32) * (T_ + 1) + s], s1);
        }
        __syncwarp();

        // softmax over the 64 d values (2 per lane)
        float m = fmaxf(s0, s1);
        #pragma unroll
        for (int o = 16; o > 0; o >>= 1) m = fmaxf(m, __shfl_xor_sync(0xffffffffu, m, o));
        float e0 = __expf(s0 - m), e1 = __expf(s1 - m);
        float sum = e0 + e1;
        #pragma unroll
        for (int o = 16; o > 0; o >>= 1) sum += __shfl_xor_sync(0xffffffffu, sum, o);
        float inv = 1.f / sum;
        arow_base[c * C_ + lane]      = e0 * inv;
        arow_base[c * C_ + lane + 32] = e1 * inv;
    }
}

// ---------------------------------------------------------------------------
// Kernel 3: out[b,c,j] = sum_i att[b,c,i] * sig[b,i,j]   (j = flattened n,t)
// Block = (batch b, 128-column tile). 256 threads = 8 row-groups x 32 col-
// threads; thread owns 8 rows x 4 cols. Packed fma.rn.f32x2 doubles fp32
// throughput (FFMA rt_SMSP=2 would otherwise cap at 64 FMA/cyc/SM).
// att is prepacked (hi=lo) into smem as u64; signals tile staged in smem.
// ---------------------------------------------------------------------------
__global__ void __launch_bounds__(256) k_mix_kernel(
    const float* __restrict__ sig, float* __restrict__ out)
{
    extern __shared__ unsigned long long smem_raw[];
    unsigned long long* att2 = smem_raw;                       // 4096 u64 = 32 KB
    float* ssm = (float*)(smem_raw + C_ * C_);                 // 64x128 f32 = 32 KB

    const int tid  = threadIdx.x;
    const int b    = blockIdx.y;
    const int col0 = blockIdx.x * 128;

    // Pack att[b] into duplicated f32x2 lanes
    const float* ab = g_att + b * (C_ * C_);
    #pragma unroll 4
    for (int i = tid; i < C_ * C_; i += 256) {
        unsigned int ai = __float_as_uint(ab[i]);
        att2[i] = ((unsigned long long)ai << 32) | (unsigned long long)ai;
    }

    // Stage signals tile [64 rows(i) x 128 cols], float4 coalesced
    const float* sb = sig + (size_t)b * (C_ * NT_) + col0;
    float4* ssm4 = (float4*)ssm;
    #pragma unroll
    for (int i = tid; i < 64 * 32; i += 256) {
        int row = i >> 5, cv = i & 31;
        ssm4[row * 32 + cv] = *(const float4*)(sb + (size_t)row * NT_ + cv * 4);
    }
    __syncthreads();

    const int ct = tid & 31;    // column group: cols ct*4 .. ct*4+3
    const int rg = tid >> 5;    // row group:    rows rg*8 .. rg*8+7

    const unsigned long long* s2 = (const unsigned long long*)ssm + ct * 2;
    const unsigned long long* ap = att2 + (rg * 8) * C_;

    unsigned long long acc[8][2];
    #pragma unroll
    for (int r = 0; r < 8; r++) { acc[r][0] = 0ull; acc[r][1] = 0ull; }

    #pragma unroll 4
    for (int i = 0; i < C_; i++) {
        unsigned long long sv0 = s2[i * 64];       // row stride = 128 f32 = 64 u64
        unsigned long long sv1 = s2[i * 64 + 1];
        #pragma unroll
        for (int r = 0; r < 8; r++) {
            unsigned long long a = ap[r * C_ + i]; // warp-uniform -> LDS broadcast
            asm("fma.rn.f32x2 %0, %1, %2, %0;" : "+l"(acc[r][0]) : "l"(a), "l"(sv0));
            asm("fma.rn.f32x2 %0, %1, %2, %0;" : "+l"(acc[r][1]) : "l"(a), "l"(sv1));
        }
    }

    float* ob = out + (size_t)(b * C_ + rg * 8) * NT_ + col0 + ct * 4;
    #pragma unroll
    for (int r = 0; r < 8; r++) {
        float4 v;
        v.x = __uint_as_float((unsigned int)(acc[r][0]));
        v.y = __uint_as_float((unsigned int)(acc[r][0] >> 32));
        v.z = __uint_as_float((unsigned int)(acc[r][1]));
        v.w = __uint_as_float((unsigned int)(acc[r][1] >> 32));
        *(float4*)(ob + (size_t)r * NT_) = v;
    }
}

// ---------------------------------------------------------------------------
extern "C" void kernel_launch(void* const* d_in, const int* in_sizes, int n_in,
                              void* d_out, int out_size)
{
    const float* sig   = (const float*)d_in[0];   // [16,64,512,128]
    const float* Wc    = (const float*)d_in[1];   // [128,128]
    const float* alpha = (const float*)d_in[2];   // [512]
    float* out = (float*)d_out;

    // 64 KB dynamic smem for k_mix (not stream-ordered; capture-safe, no alloc)
    cudaFuncSetAttribute(k_mix_kernel,
                         cudaFuncAttributeMaxDynamicSharedMemorySize, 64 * 1024);

    k_reduce_kernel<<<B_ * C_, 128>>>(sig, alpha);
    k_att_kernel<<<B_, 256>>>(Wc);
    dim3 g3(NT_ / 128, B_);
    k_mix_kernel<<<g3, 256, 64 * 1024>>>(sig, out);
}

// round 5
// speedup vs baseline: 1.2457x; 1.2457x over previous
#include <cuda_runtime.h>

#define B_  16
#define C_  64
#define N_  512
#define T_  128
#define NT_ (N_ * T_)   // 65536

typedef unsigned long long u64;

// Scratch (device globals — no allocation allowed in kernel_launch)
__device__ float g_k[B_ * C_ * T_];                       // [16,64,128]
__device__ __align__(16) u64 g_att2[B_ * C_ * C_];        // [b][i][r], dup f32x2

// ---------------------------------------------------------------------------
// Kernel 1: k[b,c,t] = sum_n signals[b,c,n,t] * alpha[n]
// 256 threads: n-range split in two halves (h), t = tid&127. Unroll 8 -> 8
// independent LDGs in flight per thread; 2x warps vs previous version.
// ---------------------------------------------------------------------------
__global__ void __launch_bounds__(256) k_reduce_kernel(
    const float* __restrict__ sig, const float* __restrict__ alpha)
{
    __shared__ float al[N_];
    __shared__ float red[128];
    const int tid = threadIdx.x;
    #pragma unroll
    for (int i = tid; i < N_; i += 256) al[i] = alpha[i];
    __syncthreads();

    const int bc = blockIdx.x;
    const int t  = tid & 127;
    const int h  = tid >> 7;              // 0 or 1: n in [h*256, h*256+256)

    const float* p  = sig + (size_t)bc * NT_ + (size_t)(h * 256) * T_ + t;
    const float* av = al + h * 256;

    float a[8];
    #pragma unroll
    for (int j = 0; j < 8; j++) a[j] = 0.f;

    #pragma unroll 4
    for (int n = 0; n < 256; n += 8) {
        #pragma unroll
        for (int j = 0; j < 8; j++)
            a[j] = fmaf(p[(size_t)(n + j) * T_], av[n + j], a[j]);
    }
    float s = ((a[0] + a[1]) + (a[2] + a[3])) + ((a[4] + a[5]) + (a[6] + a[7]));

    if (h == 1) red[t] = s;
    __syncthreads();
    if (h == 0) g_k[bc * T_ + t] = s + red[t];
}

// ---------------------------------------------------------------------------
// Kernel 2: scores[b,c,d] = k[b,c,:] @ Wc @ k[b,d,:], softmax over d.
// Grid = 16 batches x 8 row-octets; 8 warps/block, one row c per warp.
// Emits att directly in transposed + f32x2-duplicated form: g_att2[b][d][c].
// ---------------------------------------------------------------------------
__global__ void __launch_bounds__(256) k_att_kernel(const float* __restrict__ Wc)
{
    __shared__ float kk[C_ * (T_ + 1)];   // 64 x 129 (conflict-free)
    __shared__ float srow[8][T_ + 4];

    const int b    = blockIdx.x >> 3;
    const int rgrp = blockIdx.x & 7;
    const int tid  = threadIdx.x;
    const int lane = tid & 31;
    const int w    = tid >> 5;

    const float* kb = g_k + b * (C_ * T_);
    for (int i = tid; i < C_ * T_; i += 256) {
        int c = i >> 7, t = i & 127;
        kk[c * (T_ + 1) + t] = kb[i];
    }
    __syncthreads();

    const int c = rgrp * 8 + w;           // this warp's row

    // kW[c, lane*4..+3] = sum_t k[c,t] * Wc[t, lane*4..+3]
    float kw0 = 0.f, kw1 = 0.f, kw2 = 0.f, kw3 = 0.f;
    const float4* W4 = (const float4*)Wc;
    #pragma unroll 4
    for (int t = 0; t < T_; t++) {
        float4 wv = __ldg(&W4[t * 32 + lane]);
        float kc = kk[c * (T_ + 1) + t];  // warp-uniform broadcast
        kw0 = fmaf(kc, wv.x, kw0);
        kw1 = fmaf(kc, wv.y, kw1);
        kw2 = fmaf(kc, wv.z, kw2);
        kw3 = fmaf(kc, wv.w, kw3);
    }
    srow[w][lane * 4 + 0] = kw0;
    srow[w][lane * 4 + 1] = kw1;
    srow[w][lane * 4 + 2] = kw2;
    srow[w][lane * 4 + 3] = kw3;
    __syncwarp();

    // scores[c,d] for d = lane, lane+32
    float s0 = 0.f, s1 = 0.f;
    #pragma unroll 4
    for (int s = 0; s < T_; s++) {
        float v = srow[w][s];
        s0 = fmaf(v, kk[lane * (T_ + 1) + s], s0);
        s1 = fmaf(v, kk[(lane + 32) * (T_ + 1) + s], s1);
    }
    __syncwarp();

    // softmax over the 64 d values (2 per lane)
    float m = fmaxf(s0, s1);
    #pragma unroll
    for (int o = 16; o > 0; o >>= 1) m = fmaxf(m, __shfl_xor_sync(0xffffffffu, m, o));
    float e0 = __expf(s0 - m), e1 = __expf(s1 - m);
    float sum = e0 + e1;
    #pragma unroll
    for (int o = 16; o > 0; o >>= 1) sum += __shfl_xor_sync(0xffffffffu, sum, o);
    float inv = 1.f / sum;

    unsigned int p0 = __float_as_uint(e0 * inv);
    unsigned int p1 = __float_as_uint(e1 * inv);
    u64* ga = g_att2 + b * (C_ * C_);
    ga[(size_t)lane * C_ + c]        = ((u64)p0 << 32) | (u64)p0;  // [d=lane][c]
    ga[(size_t)(lane + 32) * C_ + c] = ((u64)p1 << 32) | (u64)p1;  // [d=lane+32][c]
}

// ---------------------------------------------------------------------------
// Kernel 3: out[b,c,j] = sum_i att[b,c,i] * sig[b,i,j]
// Block = 128 threads (4 warps), batch b x 128-col tile. Warp w owns rows
// w*16..w*16+15; thread owns 16 rows x 4 cols. att staged transposed+dup so
// per-i att broadcasts come 2 rows per LDS.128 (8 accesses / warp / i vs 16),
// and sv is a single LDS.128 reused across all 16 rows (.reuse-friendly).
// ---------------------------------------------------------------------------
__global__ void __launch_bounds__(128) k_mix_kernel(
    const float* __restrict__ sig, float* __restrict__ out)
{
    extern __shared__ __align__(16) u64 smem_raw[];
    u64*   att2 = smem_raw;                    // [i][r] dup u64: 4096 = 32 KB
    float* ssm  = (float*)(smem_raw + C_ * C_); // [i][col]: 64x128 f32 = 32 KB

    const int tid  = threadIdx.x;
    const int b    = blockIdx.y;
    const int col0 = blockIdx.x * 128;

    // Stage att (already transposed+dup in gmem, L2-resident: 512 KB total)
    const u64* ga = g_att2 + b * (C_ * C_);
    #pragma unroll
    for (int i = tid; i < C_ * C_; i += 128) att2[i] = ga[i];

    // Stage signals tile [64 rows(i) x 128 cols], float4 coalesced
    const float* sb = sig + (size_t)b * (C_ * NT_) + col0;
    float4* ssm4 = (float4*)ssm;
    #pragma unroll
    for (int i = tid; i < 64 * 32; i += 128) {
        int row = i >> 5, cv = i & 31;
        ssm4[row * 32 + cv] = *(const float4*)(sb + (size_t)row * NT_ + cv * 4);
    }
    __syncthreads();

    const int ct = tid & 31;    // cols ct*4 .. ct*4+3
    const int w  = tid >> 5;    // rows w*16 .. w*16+15

    const u64* svp = (const u64*)ssm + ct * 2;

    u64 acc[16][2];
    #pragma unroll
    for (int r = 0; r < 16; r++) { acc[r][0] = 0ull; acc[r][1] = 0ull; }

    #pragma unroll 4
    for (int i = 0; i < C_; i++) {
        const ulonglong2 sv = *(const ulonglong2*)(svp + (size_t)i * 64);
        const ulonglong2* ai2 = (const ulonglong2*)(att2 + i * C_ + w * 16);
        #pragma unroll
        for (int rr = 0; rr < 8; rr++) {
            ulonglong2 a2 = ai2[rr];   // broadcast: 2 rows' dup att per LDS.128
            asm("fma.rn.f32x2 %0, %1, %2, %0;" : "+l"(acc[2*rr  ][0]) : "l"(a2.x), "l"(sv.x));
            asm("fma.rn.f32x2 %0, %1, %2, %0;" : "+l"(acc[2*rr  ][1]) : "l"(a2.x), "l"(sv.y));
            asm("fma.rn.f32x2 %0, %1, %2, %0;" : "+l"(acc[2*rr+1][0]) : "l"(a2.y), "l"(sv.x));
            asm("fma.rn.f32x2 %0, %1, %2, %0;" : "+l"(acc[2*rr+1][1]) : "l"(a2.y), "l"(sv.y));
        }
    }

    float* ob = out + (size_t)(b * C_ + w * 16) * NT_ + col0 + ct * 4;
    #pragma unroll
    for (int r = 0; r < 16; r++) {
        float4 v;
        v.x = __uint_as_float((unsigned int)(acc[r][0]));
        v.y = __uint_as_float((unsigned int)(acc[r][0] >> 32));
        v.z = __uint_as_float((unsigned int)(acc[r][1]));
        v.w = __uint_as_float((unsigned int)(acc[r][1] >> 32));
        *(float4*)(ob + (size_t)r * NT_) = v;
    }
}

// ---------------------------------------------------------------------------
extern "C" void kernel_launch(void* const* d_in, const int* in_sizes, int n_in,
                              void* d_out, int out_size)
{
    const float* sig   = (const float*)d_in[0];   // [16,64,512,128]
    const float* Wc    = (const float*)d_in[1];   // [128,128]
    const float* alpha = (const float*)d_in[2];   // [512]
    float* out = (float*)d_out;

    cudaFuncSetAttribute(k_mix_kernel,
                         cudaFuncAttributeMaxDynamicSharedMemorySize, 64 * 1024);

    k_reduce_kernel<<<B_ * C_, 256>>>(sig, alpha);
    k_att_kernel<<<B_ * 8, 256>>>(Wc);
    dim3 g3(NT_ / 128, B_);
    k_mix_kernel<<<g3, 128, 64 * 1024>>>(sig, out);
}

// round 7
// speedup vs baseline: 1.2458x; 1.0001x over previous
#include <cuda_runtime.h>

#define B_  16
#define C_  64
#define N_  512
#define T_  128
#define NT_ (N_ * T_)   // 65536

typedef unsigned long long u64;

// Scratch (device globals — no allocation allowed in kernel_launch)
__device__ float g_k[B_ * C_ * T_];                       // [16,64,128]
__device__ __align__(16) u64 g_att2[B_ * C_ * C_];        // [b][i][r], dup f32x2

// ---------------------------------------------------------------------------
// Kernel 1: k[b,c,t] = sum_n signals[b,c,n,t] * alpha[n]
// 256 threads: n-range split in two halves (h), t = tid&127. Unroll 8 -> 8
// independent LDGs in flight per thread; 2x warps vs previous version.
// ---------------------------------------------------------------------------
__global__ void __launch_bounds__(256) k_reduce_kernel(
    const float* __restrict__ sig, const float* __restrict__ alpha)
{
    __shared__ float al[N_];
    __shared__ float red[128];
    const int tid = threadIdx.x;
    #pragma unroll
    for (int i = tid; i < N_; i += 256) al[i] = alpha[i];
    __syncthreads();

    const int bc = blockIdx.x;
    const int t  = tid & 127;
    const int h  = tid >> 7;              // 0 or 1: n in [h*256, h*256+256)

    const float* p  = sig + (size_t)bc * NT_ + (size_t)(h * 256) * T_ + t;
    const float* av = al + h * 256;

    float a[8];
    #pragma unroll
    for (int j = 0; j < 8; j++) a[j] = 0.f;

    #pragma unroll 4
    for (int n = 0; n < 256; n += 8) {
        #pragma unroll
        for (int j = 0; j < 8; j++)
            a[j] = fmaf(p[(size_t)(n + j) * T_], av[n + j], a[j]);
    }
    float s = ((a[0] + a[1]) + (a[2] + a[3])) + ((a[4] + a[5]) + (a[6] + a[7]));

    if (h == 1) red[t] = s;
    __syncthreads();
    if (h == 0) g_k[bc * T_ + t] = s + red[t];
}

// ---------------------------------------------------------------------------
// Kernel 2: scores[b,c,d] = k[b,c,:] @ Wc @ k[b,d,:], softmax over d.
// Grid = 16 batches x 8 row-octets; 8 warps/block, one row c per warp.
// Emits att directly in transposed + f32x2-duplicated form: g_att2[b][d][c].
// ---------------------------------------------------------------------------
__global__ void __launch_bounds__(256) k_att_kernel(const float* __restrict__ Wc)
{
    __shared__ float kk[C_ * (T_ + 1)];   // 64 x 129 (conflict-free)
    __shared__ float srow[8][T_ + 4];

    const int b    = blockIdx.x >> 3;
    const int rgrp = blockIdx.x & 7;
    const int tid  = threadIdx.x;
    const int lane = tid & 31;
    const int w    = tid >> 5;

    const float* kb = g_k + b * (C_ * T_);
    for (int i = tid; i < C_ * T_; i += 256) {
        int c = i >> 7, t = i & 127;
        kk[c * (T_ + 1) + t] = kb[i];
    }
    __syncthreads();

    const int c = rgrp * 8 + w;           // this warp's row

    // kW[c, lane*4..+3] = sum_t k[c,t] * Wc[t, lane*4..+3]
    float kw0 = 0.f, kw1 = 0.f, kw2 = 0.f, kw3 = 0.f;
    const float4* W4 = (const float4*)Wc;
    #pragma unroll 4
    for (int t = 0; t < T_; t++) {
        float4 wv = __ldg(&W4[t * 32 + lane]);
        float kc = kk[c * (T_ + 1) + t];  // warp-uniform broadcast
        kw0 = fmaf(kc, wv.x, kw0);
        kw1 = fmaf(kc, wv.y, kw1);
        kw2 = fmaf(kc, wv.z, kw2);
        kw3 = fmaf(kc, wv.w, kw3);
    }
    srow[w][lane * 4 + 0] = kw0;
    srow[w][lane * 4 + 1] = kw1;
    srow[w][lane * 4 + 2] = kw2;
    srow[w][lane * 4 + 3] = kw3;
    __syncwarp();

    // scores[c,d] for d = lane, lane+32
    float s0 = 0.f, s1 = 0.f;
    #pragma unroll 4
    for (int s = 0; s < T_; s++) {
        float v = srow[w][s];
        s0 = fmaf(v, kk[lane * (T_ + 1) + s], s0);
        s1 = fmaf(v, kk[(lane + 32) * (T_ + 1) + s], s1);
    }
    __syncwarp();

    // softmax over the 64 d values (2 per lane)
    float m = fmaxf(s0, s1);
    #pragma unroll
    for (int o = 16; o > 0; o >>= 1) m = fmaxf(m, __shfl_xor_sync(0xffffffffu, m, o));
    float e0 = __expf(s0 - m), e1 = __expf(s1 - m);
    float sum = e0 + e1;
    #pragma unroll
    for (int o = 16; o > 0; o >>= 1) sum += __shfl_xor_sync(0xffffffffu, sum, o);
    float inv = 1.f / sum;

    unsigned int p0 = __float_as_uint(e0 * inv);
    unsigned int p1 = __float_as_uint(e1 * inv);
    u64* ga = g_att2 + b * (C_ * C_);
    ga[(size_t)lane * C_ + c]        = ((u64)p0 << 32) | (u64)p0;  // [d=lane][c]
    ga[(size_t)(lane + 32) * C_ + c] = ((u64)p1 << 32) | (u64)p1;  // [d=lane+32][c]
}

// ---------------------------------------------------------------------------
// Kernel 3: out[b,c,j] = sum_i att[b,c,i] * sig[b,i,j]
// Block = 128 threads (4 warps), batch b x 128-col tile. Warp w owns rows
// w*16..w*16+15; thread owns 16 rows x 4 cols. att staged transposed+dup so
// per-i att broadcasts come 2 rows per LDS.128 (8 accesses / warp / i vs 16),
// and sv is a single LDS.128 reused across all 16 rows (.reuse-friendly).
// ---------------------------------------------------------------------------
__global__ void __launch_bounds__(128) k_mix_kernel(
    const float* __restrict__ sig, float* __restrict__ out)
{
    extern __shared__ __align__(16) u64 smem_raw[];
    u64*   att2 = smem_raw;                    // [i][r] dup u64: 4096 = 32 KB
    float* ssm  = (float*)(smem_raw + C_ * C_); // [i][col]: 64x128 f32 = 32 KB

    const int tid  = threadIdx.x;
    const int b    = blockIdx.y;
    const int col0 = blockIdx.x * 128;

    // Stage att (already transposed+dup in gmem, L2-resident: 512 KB total)
    const u64* ga = g_att2 + b * (C_ * C_);
    #pragma unroll
    for (int i = tid; i < C_ * C_; i += 128) att2[i] = ga[i];

    // Stage signals tile [64 rows(i) x 128 cols], float4 coalesced
    const float* sb = sig + (size_t)b * (C_ * NT_) + col0;
    float4* ssm4 = (float4*)ssm;
    #pragma unroll
    for (int i = tid; i < 64 * 32; i += 128) {
        int row = i >> 5, cv = i & 31;
        ssm4[row * 32 + cv] = *(const float4*)(sb + (size_t)row * NT_ + cv * 4);
    }
    __syncthreads();

    const int ct = tid & 31;    // cols ct*4 .. ct*4+3
    const int w  = tid >> 5;    // rows w*16 .. w*16+15

    const u64* svp = (const u64*)ssm + ct * 2;

    u64 acc[16][2];
    #pragma unroll
    for (int r = 0; r < 16; r++) { acc[r][0] = 0ull; acc[r][1] = 0ull; }

    #pragma unroll 4
    for (int i = 0; i < C_; i++) {
        const ulonglong2 sv = *(const ulonglong2*)(svp + (size_t)i * 64);
        const ulonglong2* ai2 = (const ulonglong2*)(att2 + i * C_ + w * 16);
        #pragma unroll
        for (int rr = 0; rr < 8; rr++) {
            ulonglong2 a2 = ai2[rr];   // broadcast: 2 rows' dup att per LDS.128
            asm("fma.rn.f32x2 %0, %1, %2, %0;" : "+l"(acc[2*rr  ][0]) : "l"(a2.x), "l"(sv.x));
            asm("fma.rn.f32x2 %0, %1, %2, %0;" : "+l"(acc[2*rr  ][1]) : "l"(a2.x), "l"(sv.y));
            asm("fma.rn.f32x2 %0, %1, %2, %0;" : "+l"(acc[2*rr+1][0]) : "l"(a2.y), "l"(sv.x));
            asm("fma.rn.f32x2 %0, %1, %2, %0;" : "+l"(acc[2*rr+1][1]) : "l"(a2.y), "l"(sv.y));
        }
    }

    float* ob = out + (size_t)(b * C_ + w * 16) * NT_ + col0 + ct * 4;
    #pragma unroll
    for (int r = 0; r < 16; r++) {
        float4 v;
        v.x = __uint_as_float((unsigned int)(acc[r][0]));
        v.y = __uint_as_float((unsigned int)(acc[r][0] >> 32));
        v.z = __uint_as_float((unsigned int)(acc[r][1]));
        v.w = __uint_as_float((unsigned int)(acc[r][1] >> 32));
        *(float4*)(ob + (size_t)r * NT_) = v;
    }
}

// ---------------------------------------------------------------------------
extern "C" void kernel_launch(void* const* d_in, const int* in_sizes, int n_in,
                              void* d_out, int out_size)
{
    const float* sig   = (const float*)d_in[0];   // [16,64,512,128]
    const float* Wc    = (const float*)d_in[1];   // [128,128]
    const float* alpha = (const float*)d_in[2];   // [512]
    float* out = (float*)d_out;

    cudaFuncSetAttribute(k_mix_kernel,
                         cudaFuncAttributeMaxDynamicSharedMemorySize, 64 * 1024);

    k_reduce_kernel<<<B_ * C_, 256>>>(sig, alpha);
    k_att_kernel<<<B_ * 8, 256>>>(Wc);
    dim3 g3(NT_ / 128, B_);
    k_mix_kernel<<<g3, 128, 64 * 1024>>>(sig, out);
}

// round 8
// speedup vs baseline: 1.2468x; 1.0008x over previous
#include <cuda_runtime.h>

#define B_  16
#define C_  64
#define N_  512
#define T_  128
#define NT_ (N_ * T_)   // 65536

typedef unsigned long long u64;

// Scratch (device globals — no allocation allowed in kernel_launch)
__device__ float g_k[B_ * C_ * T_];                       // [16,64,128]
__device__ __align__(16) u64 g_att2[B_ * C_ * C_];        // [b][i][r], dup f32x2

// ---------------------------------------------------------------------------
// Kernel 1: k[b,c,t] = sum_n signals[b,c,n,t] * alpha[n]
// 256 threads: n-range split in two halves (h), t = tid&127. Unroll 8 -> 8
// independent LDGs in flight per thread; 2x warps vs previous version.
// ---------------------------------------------------------------------------
__global__ void __launch_bounds__(256) k_reduce_kernel(
    const float* __restrict__ sig, const float* __restrict__ alpha)
{
    __shared__ float al[N_];
    __shared__ float red[128];
    const int tid = threadIdx.x;
    #pragma unroll
    for (int i = tid; i < N_; i += 256) al[i] = alpha[i];
    __syncthreads();

    const int bc = blockIdx.x;
    const int t  = tid & 127;
    const int h  = tid >> 7;              // 0 or 1: n in [h*256, h*256+256)

    const float* p  = sig + (size_t)bc * NT_ + (size_t)(h * 256) * T_ + t;
    const float* av = al + h * 256;

    float a[8];
    #pragma unroll
    for (int j = 0; j < 8; j++) a[j] = 0.f;

    #pragma unroll 4
    for (int n = 0; n < 256; n += 8) {
        #pragma unroll
        for (int j = 0; j < 8; j++)
            a[j] = fmaf(p[(size_t)(n + j) * T_], av[n + j], a[j]);
    }
    float s = ((a[0] + a[1]) + (a[2] + a[3])) + ((a[4] + a[5]) + (a[6] + a[7]));

    if (h == 1) red[t] = s;
    __syncthreads();
    if (h == 0) g_k[bc * T_ + t] = s + red[t];
}

// ---------------------------------------------------------------------------
// Kernel 2: scores[b,c,d] = k[b,c,:] @ Wc @ k[b,d,:], softmax over d.
// Grid = 16 batches x 8 row-octets; 8 warps/block, one row c per warp.
// Emits att directly in transposed + f32x2-duplicated form: g_att2[b][d][c].
// ---------------------------------------------------------------------------
__global__ void __launch_bounds__(256) k_att_kernel(const float* __restrict__ Wc)
{
    __shared__ float kk[C_ * (T_ + 1)];   // 64 x 129 (conflict-free)
    __shared__ float srow[8][T_ + 4];

    const int b    = blockIdx.x >> 3;
    const int rgrp = blockIdx.x & 7;
    const int tid  = threadIdx.x;
    const int lane = tid & 31;
    const int w    = tid >> 5;

    const float* kb = g_k + b * (C_ * T_);
    for (int i = tid; i < C_ * T_; i += 256) {
        int c = i >> 7, t = i & 127;
        kk[c * (T_ + 1) + t] = kb[i];
    }
    __syncthreads();

    const int c = rgrp * 8 + w;           // this warp's row

    // kW[c, lane*4..+3] = sum_t k[c,t] * Wc[t, lane*4..+3]
    float kw0 = 0.f, kw1 = 0.f, kw2 = 0.f, kw3 = 0.f;
    const float4* W4 = (const float4*)Wc;
    #pragma unroll 4
    for (int t = 0; t < T_; t++) {
        float4 wv = __ldg(&W4[t * 32 + lane]);
        float kc = kk[c * (T_ + 1) + t];  // warp-uniform broadcast
        kw0 = fmaf(kc, wv.x, kw0);
        kw1 = fmaf(kc, wv.y, kw1);
        kw2 = fmaf(kc, wv.z, kw2);
        kw3 = fmaf(kc, wv.w, kw3);
    }
    srow[w][lane * 4 + 0] = kw0;
    srow[w][lane * 4 + 1] = kw1;
    srow[w][lane * 4 + 2] = kw2;
    srow[w][lane * 4 + 3] = kw3;
    __syncwarp();

    // scores[c,d] for d = lane, lane+32
    float s0 = 0.f, s1 = 0.f;
    #pragma unroll 4
    for (int s = 0; s < T_; s++) {
        float v = srow[w][s];
        s0 = fmaf(v, kk[lane * (T_ + 1) + s], s0);
        s1 = fmaf(v, kk[(lane + 32) * (T_ + 1) + s], s1);
    }
    __syncwarp();

    // softmax over the 64 d values (2 per lane)
    float m = fmaxf(s0, s1);
    #pragma unroll
    for (int o = 16; o > 0; o >>= 1) m = fmaxf(m, __shfl_xor_sync(0xffffffffu, m, o));
    float e0 = __expf(s0 - m), e1 = __expf(s1 - m);
    float sum = e0 + e1;
    #pragma unroll
    for (int o = 16; o > 0; o >>= 1) sum += __shfl_xor_sync(0xffffffffu, sum, o);
    float inv = 1.f / sum;

    unsigned int p0 = __float_as_uint(e0 * inv);
    unsigned int p1 = __float_as_uint(e1 * inv);
    u64* ga = g_att2 + b * (C_ * C_);
    ga[(size_t)lane * C_ + c]        = ((u64)p0 << 32) | (u64)p0;  // [d=lane][c]
    ga[(size_t)(lane + 32) * C_ + c] = ((u64)p1 << 32) | (u64)p1;  // [d=lane+32][c]
}

// ---------------------------------------------------------------------------
// Kernel 3: out[b,c,j] = sum_i att[b,c,i] * sig[b,i,j]
// Block = 128 threads (4 warps), batch b x 128-col tile. Warp w owns rows
// w*16..w*16+15; thread owns 16 rows x 4 cols. att staged transposed+dup so
// per-i att broadcasts come 2 rows per LDS.128 (8 accesses / warp / i vs 16),
// and sv is a single LDS.128 reused across all 16 rows (.reuse-friendly).
// ---------------------------------------------------------------------------
__global__ void __launch_bounds__(128) k_mix_kernel(
    const float* __restrict__ sig, float* __restrict__ out)
{
    extern __shared__ __align__(16) u64 smem_raw[];
    u64*   att2 = smem_raw;                    // [i][r] dup u64: 4096 = 32 KB
    float* ssm  = (float*)(smem_raw + C_ * C_); // [i][col]: 64x128 f32 = 32 KB

    const int tid  = threadIdx.x;
    const int b    = blockIdx.y;
    const int col0 = blockIdx.x * 128;

    // Stage att (already transposed+dup in gmem, L2-resident: 512 KB total)
    const u64* ga = g_att2 + b * (C_ * C_);
    #pragma unroll
    for (int i = tid; i < C_ * C_; i += 128) att2[i] = ga[i];

    // Stage signals tile [64 rows(i) x 128 cols], float4 coalesced
    const float* sb = sig + (size_t)b * (C_ * NT_) + col0;
    float4* ssm4 = (float4*)ssm;
    #pragma unroll
    for (int i = tid; i < 64 * 32; i += 128) {
        int row = i >> 5, cv = i & 31;
        ssm4[row * 32 + cv] = *(const float4*)(sb + (size_t)row * NT_ + cv * 4);
    }
    __syncthreads();

    const int ct = tid & 31;    // cols ct*4 .. ct*4+3
    const int w  = tid >> 5;    // rows w*16 .. w*16+15

    const u64* svp = (const u64*)ssm + ct * 2;

    u64 acc[16][2];
    #pragma unroll
    for (int r = 0; r < 16; r++) { acc[r][0] = 0ull; acc[r][1] = 0ull; }

    #pragma unroll 4
    for (int i = 0; i < C_; i++) {
        const ulonglong2 sv = *(const ulonglong2*)(svp + (size_t)i * 64);
        const ulonglong2* ai2 = (const ulonglong2*)(att2 + i * C_ + w * 16);
        #pragma unroll
        for (int rr = 0; rr < 8; rr++) {
            ulonglong2 a2 = ai2[rr];   // broadcast: 2 rows' dup att per LDS.128
            asm("fma.rn.f32x2 %0, %1, %2, %0;" : "+l"(acc[2*rr  ][0]) : "l"(a2.x), "l"(sv.x));
            asm("fma.rn.f32x2 %0, %1, %2, %0;" : "+l"(acc[2*rr  ][1]) : "l"(a2.x), "l"(sv.y));
            asm("fma.rn.f32x2 %0, %1, %2, %0;" : "+l"(acc[2*rr+1][0]) : "l"(a2.y), "l"(sv.x));
            asm("fma.rn.f32x2 %0, %1, %2, %0;" : "+l"(acc[2*rr+1][1]) : "l"(a2.y), "l"(sv.y));
        }
    }

    float* ob = out + (size_t)(b * C_ + w * 16) * NT_ + col0 + ct * 4;
    #pragma unroll
    for (int r = 0; r < 16; r++) {
        float4 v;
        v.x = __uint_as_float((unsigned int)(acc[r][0]));
        v.y = __uint_as_float((unsigned int)(acc[r][0] >> 32));
        v.z = __uint_as_float((unsigned int)(acc[r][1]));
        v.w = __uint_as_float((unsigned int)(acc[r][1] >> 32));
        *(float4*)(ob + (size_t)r * NT_) = v;
    }
}

// ---------------------------------------------------------------------------
extern "C" void kernel_launch(void* const* d_in, const int* in_sizes, int n_in,
                              void* d_out, int out_size)
{
    const float* sig   = (const float*)d_in[0];   // [16,64,512,128]
    const float* Wc    = (const float*)d_in[1];   // [128,128]
    const float* alpha = (const float*)d_in[2];   // [512]
    float* out = (float*)d_out;

    cudaFuncSetAttribute(k_mix_kernel,
                         cudaFuncAttributeMaxDynamicSharedMemorySize, 64 * 1024);

    k_reduce_kernel<<<B_ * C_, 256>>>(sig, alpha);
    k_att_kernel<<<B_ * 8, 256>>>(Wc);
    dim3 g3(NT_ / 128, B_);
    k_mix_kernel<<<g3, 128, 64 * 1024>>>(sig, out);
}

// round 9
// speedup vs baseline: 1.3940x; 1.1180x over previous
#include <cuda_runtime.h>

#define B_  16
#define C_  64
#define N_  512
#define T_  128
#define NT_ (N_ * T_)   // 65536

// Scratch (device globals — no allocation allowed in kernel_launch)
__device__ float g_k[B_ * C_ * T_];     // [16,64,128]
__device__ float g_att[B_ * C_ * C_];   // [16,64,64] plain f32

// ---------------------------------------------------------------------------
// tf32 2-term split: x ~= hi + lo, both exactly representable in tf32.
// hi*hi' + hi*lo' + lo*hi' reproduces x*x' to ~2^-21 relative.
// ---------------------------------------------------------------------------
__device__ __forceinline__ void tf32_split(float x, float& hi, float& lo) {
    unsigned h, l;
    asm("cvt.rna.tf32.f32 %0, %1;" : "=r"(h) : "f"(x));
    hi = __uint_as_float(h);
    float r = x - hi;
    asm("cvt.rna.tf32.f32 %0, %1;" : "=r"(l) : "f"(r));
    lo = __uint_as_float(l);
}

#define MMA_TF32(d0,d1,d2,d3, a0,a1,a2,a3, b0,b1)                              \
    asm volatile("mma.sync.aligned.m16n8k8.row.col.f32.tf32.tf32.f32 "         \
        "{%0,%1,%2,%3}, {%4,%5,%6,%7}, {%8,%9}, {%0,%1,%2,%3};"                \
        : "+f"(d0), "+f"(d1), "+f"(d2), "+f"(d3)                               \
        : "r"(__float_as_uint(a0)), "r"(__float_as_uint(a1)),                  \
          "r"(__float_as_uint(a2)), "r"(__float_as_uint(a3)),                  \
          "r"(__float_as_uint(b0)), "r"(__float_as_uint(b1)))

// ---------------------------------------------------------------------------
// Kernel 1: k[b,c,t] = sum_n signals[b,c,n,t] * alpha[n]
// 256 threads: thread (g=tid>>5, q=tid&31) accumulates float4 column q over
// rows n = g + 8m. 8 LDG.128 in flight per thread (unroll 8).
// ---------------------------------------------------------------------------
__global__ void __launch_bounds__(256) k_reduce_kernel(
    const float* __restrict__ sig, const float* __restrict__ alpha)
{
    __shared__ float  al[N_];
    __shared__ float4 sred[8][32];
    const int tid = threadIdx.x;
    #pragma unroll
    for (int i = tid; i < N_; i += 256) al[i] = alpha[i];
    __syncthreads();

    const int bc = blockIdx.x;
    const int q  = tid & 31;
    const int g  = tid >> 5;

    // row n occupies 32 float4; thread reads f4 index n*32 + q
    const float4* p = (const float4*)(sig + (size_t)bc * NT_) + g * 32 + q;

    float4 acc = make_float4(0.f, 0.f, 0.f, 0.f);
    #pragma unroll 8
    for (int m = 0; m < 64; m++) {
        float  av = al[g + 8 * m];
        float4 v  = p[(size_t)m * 256];     // step 8 rows = 256 f4
        acc.x = fmaf(v.x, av, acc.x);
        acc.y = fmaf(v.y, av, acc.y);
        acc.z = fmaf(v.z, av, acc.z);
        acc.w = fmaf(v.w, av, acc.w);
    }
    sred[g][q] = acc;
    __syncthreads();

    if (tid < 32) {
        float4 s = sred[0][tid];
        #pragma unroll
        for (int gg = 1; gg < 8; gg++) {
            float4 v = sred[gg][tid];
            s.x += v.x; s.y += v.y; s.z += v.z; s.w += v.w;
        }
        ((float4*)(g_k + bc * T_))[tid] = s;
    }
}

// ---------------------------------------------------------------------------
// Kernel 2: scores[b,c,d] = k[b,c,:] @ Wc @ k[b,d,:], softmax over d.
// Grid = 16 batches x 8 row-octets; one row c per warp. Plain f32 att out.
// ---------------------------------------------------------------------------
__global__ void __launch_bounds__(256) k_att_kernel(const float* __restrict__ Wc)
{
    __shared__ float kk[C_ * (T_ + 1)];
    __shared__ float srow[8][T_ + 4];

    const int b    = blockIdx.x >> 3;
    const int rgrp = blockIdx.x & 7;
    const int tid  = threadIdx.x;
    const int lane = tid & 31;
    const int w    = tid >> 5;

    const float* kb = g_k + b * (C_ * T_);
    for (int i = tid; i < C_ * T_; i += 256) {
        int c = i >> 7, t = i & 127;
        kk[c * (T_ + 1) + t] = kb[i];
    }
    __syncthreads();

    const int c = rgrp * 8 + w;

    float kw0 = 0.f, kw1 = 0.f, kw2 = 0.f, kw3 = 0.f;
    const float4* W4 = (const float4*)Wc;
    #pragma unroll 4
    for (int t = 0; t < T_; t++) {
        float4 wv = __ldg(&W4[t * 32 + lane]);
        float kc = kk[c * (T_ + 1) + t];
        kw0 = fmaf(kc, wv.x, kw0);
        kw1 = fmaf(kc, wv.y, kw1);
        kw2 = fmaf(kc, wv.z, kw2);
        kw3 = fmaf(kc, wv.w, kw3);
    }
    srow[w][lane * 4 + 0] = kw0;
    srow[w][lane * 4 + 1] = kw1;
    srow[w][lane * 4 + 2] = kw2;
    srow[w][lane * 4 + 3] = kw3;
    __syncwarp();

    float s0 = 0.f, s1 = 0.f;
    #pragma unroll 4
    for (int s = 0; s < T_; s++) {
        float v = srow[w][s];
        s0 = fmaf(v, kk[lane * (T_ + 1) + s], s0);
        s1 = fmaf(v, kk[(lane + 32) * (T_ + 1) + s], s1);
    }
    __syncwarp();

    float m = fmaxf(s0, s1);
    #pragma unroll
    for (int o = 16; o > 0; o >>= 1) m = fmaxf(m, __shfl_xor_sync(0xffffffffu, m, o));
    float e0 = __expf(s0 - m), e1 = __expf(s1 - m);
    float sum = e0 + e1;
    #pragma unroll
    for (int o = 16; o > 0; o >>= 1) sum += __shfl_xor_sync(0xffffffffu, sum, o);
    float inv = 1.f / sum;

    float* arow = g_att + b * (C_ * C_) + c * C_;
    arow[lane]      = e0 * inv;
    arow[lane + 32] = e1 * inv;
}

// ---------------------------------------------------------------------------
// Kernel 3: out[b] = att[b] (64x64) @ sig[b] (64x65536), tf32 tensor-core MMA
// with 2-term split (hi*hi + hi*lo + lo*hi) for fp32-class accuracy.
//
// Block = 128 threads (4 warps), tile = 64 c x 128 j. Warp w owns j columns
// [32w, 32w+32): 4 m-tiles (m16 over c) x 4 n-tiles (n8 over j) x 8 k-steps.
// A = att [c][i] smem pad 68 (bank = 4*gid+ctid, conflict-free).
// B = sig [i][j] smem pad 136 (bank = 8*ctid+gid, conflict-free).
// ---------------------------------------------------------------------------
#define SIG_PAD 136
#define ATT_PAD 68

__global__ void __launch_bounds__(128) k_mix_kernel(
    const float* __restrict__ sig, float* __restrict__ out)
{
    extern __shared__ float sm[];
    float* sHi  = sm;                        // [64][136]  8704
    float* sLo  = sHi + 64 * SIG_PAD;        // 8704
    float* aHiS = sLo + 64 * SIG_PAD;        // [64][68]   4352
    float* aLoS = aHiS + 64 * ATT_PAD;       // 4352      => 26112 f32 = 102 KB

    const int tid = threadIdx.x;
    const int b   = blockIdx.y;
    const int j0  = blockIdx.x * 128;

    // ---- stage att[b] (hi/lo split) ----
    const float4* ga4 = (const float4*)(g_att + b * (C_ * C_));
    #pragma unroll
    for (int idx = tid; idx < 1024; idx += 128) {
        int c = idx >> 4, i4 = idx & 15;
        float4 v = ga4[idx];
        float4 h, l;
        tf32_split(v.x, h.x, l.x);
        tf32_split(v.y, h.y, l.y);
        tf32_split(v.z, h.z, l.z);
        tf32_split(v.w, h.w, l.w);
        ((float4*)(aHiS + c * ATT_PAD))[i4] = h;
        ((float4*)(aLoS + c * ATT_PAD))[i4] = l;
    }

    // ---- stage sig tile [64 i][128 j] (hi/lo split), float4 coalesced ----
    const float* sb = sig + (size_t)b * (C_ * NT_) + j0;
    #pragma unroll
    for (int idx = tid; idx < 64 * 32; idx += 128) {
        int row = idx >> 5, q = idx & 31;
        float4 v = *(const float4*)(sb + (size_t)row * NT_ + q * 4);
        float4 h, l;
        tf32_split(v.x, h.x, l.x);
        tf32_split(v.y, h.y, l.y);
        tf32_split(v.z, h.z, l.z);
        tf32_split(v.w, h.w, l.w);
        ((float4*)(sHi + row * SIG_PAD))[q] = h;
        ((float4*)(sLo + row * SIG_PAD))[q] = l;
    }
    __syncthreads();

    const int lane = tid & 31;
    const int w    = tid >> 5;
    const int ctid = lane & 3;    // thread-in-group
    const int gid  = lane >> 2;   // group id

    float acc[4][4][4];
    #pragma unroll
    for (int m = 0; m < 4; m++)
        #pragma unroll
        for (int n = 0; n < 4; n++)
            acc[m][n][0] = acc[m][n][1] = acc[m][n][2] = acc[m][n][3] = 0.f;

    #pragma unroll 2
    for (int kk = 0; kk < 8; kk++) {
        const int i0 = kk * 8 + ctid;

        // B fragments for this k-step: 4 n-tiles, hi & lo
        float bh[4][2], bl[4][2];
        #pragma unroll
        for (int n = 0; n < 4; n++) {
            int j = w * 32 + n * 8 + gid;
            bh[n][0] = sHi[i0 * SIG_PAD + j];
            bh[n][1] = sHi[(i0 + 4) * SIG_PAD + j];
            bl[n][0] = sLo[i0 * SIG_PAD + j];
            bl[n][1] = sLo[(i0 + 4) * SIG_PAD + j];
        }

        #pragma unroll
        for (int m = 0; m < 4; m++) {
            const int c0 = m * 16 + gid;
            float ah0 = aHiS[c0 * ATT_PAD + i0];
            float ah1 = aHiS[(c0 + 8) * ATT_PAD + i0];
            float ah2 = aHiS[c0 * ATT_PAD + i0 + 4];
            float ah3 = aHiS[(c0 + 8) * ATT_PAD + i0 + 4];
            float al0 = aLoS[c0 * ATT_PAD + i0];
            float al1 = aLoS[(c0 + 8) * ATT_PAD + i0];
            float al2 = aLoS[c0 * ATT_PAD + i0 + 4];
            float al3 = aLoS[(c0 + 8) * ATT_PAD + i0 + 4];
            #pragma unroll
            for (int n = 0; n < 4; n++) {
                MMA_TF32(acc[m][n][0], acc[m][n][1], acc[m][n][2], acc[m][n][3],
                         ah0, ah1, ah2, ah3, bh[n][0], bh[n][1]);
                MMA_TF32(acc[m][n][0], acc[m][n][1], acc[m][n][2], acc[m][n][3],
                         ah0, ah1, ah2, ah3, bl[n][0], bl[n][1]);
                MMA_TF32(acc[m][n][0], acc[m][n][1], acc[m][n][2], acc[m][n][3],
                         al0, al1, al2, al3, bh[n][0], bh[n][1]);
            }
        }
    }

    // ---- write out: d0/d1 -> (c, j..j+1), d2/d3 -> (c+8, j..j+1) ----
    #pragma unroll
    for (int m = 0; m < 4; m++) {
        const int c = m * 16 + gid;
        #pragma unroll
        for (int n = 0; n < 4; n++) {
            const int j = j0 + w * 32 + n * 8 + ctid * 2;
            float* p0 = out + ((size_t)(b * C_ + c)) * NT_ + j;
            *(float2*)p0 = make_float2(acc[m][n][0], acc[m][n][1]);
            *(float2*)(p0 + (size_t)8 * NT_) = make_float2(acc[m][n][2], acc[m][n][3]);
        }
    }
}

// ---------------------------------------------------------------------------
extern "C" void kernel_launch(void* const* d_in, const int* in_sizes, int n_in,
                              void* d_out, int out_size)
{
    const float* sig   = (const float*)d_in[0];   // [16,64,512,128]
    const float* Wc    = (const float*)d_in[1];   // [128,128]
    const float* alpha = (const float*)d_in[2];   // [512]
    float* out = (float*)d_out;

    const int smem_mix = 26112 * 4;  // 104448 B
    cudaFuncSetAttribute(k_mix_kernel,
                         cudaFuncAttributeMaxDynamicSharedMemorySize, smem_mix);

    k_reduce_kernel<<<B_ * C_, 256>>>(sig, alpha);
    k_att_kernel<<<B_ * 8, 256>>>(Wc);
    dim3 g3(NT_ / 128, B_);
    k_mix_kernel<<<g3, 128, smem_mix>>>(sig, out);
}

// round 11
// speedup vs baseline: 1.8260x; 1.3099x over previous
#include <cuda_runtime.h>

#define B_  16
#define C_  64
#define N_  512
#define T_  128
#define NT_ (N_ * T_)   // 65536

#define ATT_PAD 72      // bf16 elems per att row (bank-conflict-free: 4*gid+ctid)
#define SIG_PAD 132     // f32 elems per sig row  (bank-conflict-free: 8*ctid+gid)

// Scratch (device globals — no allocation allowed in kernel_launch)
__device__ float g_k[B_ * C_ * T_];                         // [16,64,128]
__device__ unsigned short g_att_hi[B_ * C_ * ATT_PAD];      // bf16 hi (truncated)
__device__ unsigned short g_att_lo[B_ * C_ * ATT_PAD];      // bf16 lo (rn residual)

// bf16 mma: D(16x8) += A(16x16,row) * B(16x8,col), fp32 accum
#define MMA_BF16(d0,d1,d2,d3, a0,a1,a2,a3, b0,b1)                              \
    asm volatile("mma.sync.aligned.m16n8k16.row.col.f32.bf16.bf16.f32 "        \
        "{%0,%1,%2,%3}, {%4,%5,%6,%7}, {%8,%9}, {%0,%1,%2,%3};"                \
        : "+f"(d0), "+f"(d1), "+f"(d2), "+f"(d3)                               \
        : "r"(a0), "r"(a1), "r"(a2), "r"(a3), "r"(b0), "r"(b1))

// ---------------------------------------------------------------------------
// Kernel 1: k[b,c,t] = sum_n signals[b,c,n,t] * alpha[n]   (at LTS cap)
// ---------------------------------------------------------------------------
__global__ void __launch_bounds__(256) k_reduce_kernel(
    const float* __restrict__ sig, const float* __restrict__ alpha)
{
    __shared__ float  al[N_];
    __shared__ float4 sred[8][32];
    const int tid = threadIdx.x;
    #pragma unroll
    for (int i = tid; i < N_; i += 256) al[i] = alpha[i];
    __syncthreads();

    const int bc = blockIdx.x;
    const int q  = tid & 31;
    const int g  = tid >> 5;

    const float4* p = (const float4*)(sig + (size_t)bc * NT_) + g * 32 + q;

    float4 acc = make_float4(0.f, 0.f, 0.f, 0.f);
    #pragma unroll 8
    for (int m = 0; m < 64; m++) {
        float  av = al[g + 8 * m];
        float4 v  = p[(size_t)m * 256];
        acc.x = fmaf(v.x, av, acc.x);
        acc.y = fmaf(v.y, av, acc.y);
        acc.z = fmaf(v.z, av, acc.z);
        acc.w = fmaf(v.w, av, acc.w);
    }
    sred[g][q] = acc;
    __syncthreads();

    if (tid < 32) {
        float4 s = sred[0][tid];
        #pragma unroll
        for (int gg = 1; gg < 8; gg++) {
            float4 v = sred[gg][tid];
            s.x += v.x; s.y += v.y; s.z += v.z; s.w += v.w;
        }
        ((float4*)(g_k + bc * T_))[tid] = s;
    }
}

// ---------------------------------------------------------------------------
// Kernel 2: scores -> softmax -> att, emitted PRE-SPLIT as bf16 hi/lo in the
// padded [c][72] layout k_mix's A fragments want. hi = truncation (exact bf16,
// exact f32 residual), lo = rn(residual).
// ---------------------------------------------------------------------------
__global__ void __launch_bounds__(256) k_att_kernel(const float* __restrict__ Wc)
{
    __shared__ float kk[C_ * (T_ + 1)];
    __shared__ float srow[8][T_ + 4];

    const int b    = blockIdx.x >> 3;
    const int rgrp = blockIdx.x & 7;
    const int tid  = threadIdx.x;
    const int lane = tid & 31;
    const int w    = tid >> 5;

    const float* kb = g_k + b * (C_ * T_);
    for (int i = tid; i < C_ * T_; i += 256) {
        int c = i >> 7, t = i & 127;
        kk[c * (T_ + 1) + t] = kb[i];
    }
    __syncthreads();

    const int c = rgrp * 8 + w;

    float kw0 = 0.f, kw1 = 0.f, kw2 = 0.f, kw3 = 0.f;
    const float4* W4 = (const float4*)Wc;
    #pragma unroll 4
    for (int t = 0; t < T_; t++) {
        float4 wv = __ldg(&W4[t * 32 + lane]);
        float kc = kk[c * (T_ + 1) + t];
        kw0 = fmaf(kc, wv.x, kw0);
        kw1 = fmaf(kc, wv.y, kw1);
        kw2 = fmaf(kc, wv.z, kw2);
        kw3 = fmaf(kc, wv.w, kw3);
    }
    srow[w][lane * 4 + 0] = kw0;
    srow[w][lane * 4 + 1] = kw1;
    srow[w][lane * 4 + 2] = kw2;
    srow[w][lane * 4 + 3] = kw3;
    __syncwarp();

    float s0 = 0.f, s1 = 0.f;
    #pragma unroll 4
    for (int s = 0; s < T_; s++) {
        float v = srow[w][s];
        s0 = fmaf(v, kk[lane * (T_ + 1) + s], s0);
        s1 = fmaf(v, kk[(lane + 32) * (T_ + 1) + s], s1);
    }
    __syncwarp();

    float m = fmaxf(s0, s1);
    #pragma unroll
    for (int o = 16; o > 0; o >>= 1) m = fmaxf(m, __shfl_xor_sync(0xffffffffu, m, o));
    float e0 = __expf(s0 - m), e1 = __expf(s1 - m);
    float sum = e0 + e1;
    #pragma unroll
    for (int o = 16; o > 0; o >>= 1) sum += __shfl_xor_sync(0xffffffffu, sum, o);
    float inv = 1.f / sum;
    float v0 = e0 * inv, v1 = e1 * inv;

    unsigned short* ah = g_att_hi + (b * C_ + c) * ATT_PAD;
    unsigned short* al = g_att_lo + (b * C_ + c) * ATT_PAD;

    unsigned u0 = __float_as_uint(v0);
    unsigned u1 = __float_as_uint(v1);
    float l0 = v0 - __uint_as_float(u0 & 0xffff0000u);
    float l1 = v1 - __uint_as_float(u1 & 0xffff0000u);
    unsigned short lb0, lb1;
    asm("cvt.rn.bf16.f32 %0, %1;" : "=h"(lb0) : "f"(l0));
    asm("cvt.rn.bf16.f32 %0, %1;" : "=h"(lb1) : "f"(l1));
    ah[lane]      = (unsigned short)(u0 >> 16);
    ah[lane + 32] = (unsigned short)(u1 >> 16);
    al[lane]      = lb0;
    al[lane + 32] = lb1;
    // pad columns 64..71 left untouched (never consumed by MMA fragments)
}

// ---------------------------------------------------------------------------
// Kernel 3: out[b] = att[b](64x64) @ sig[b](64x65536), bf16 m16n8k16 MMA,
// 3-term split (AhBh + AhBl + AlBh). Staging is raw-f32 sig + tiny bf16 att
// copies; all splitting happens on fragments in registers (PRMT/LOP3/FSUB).
// smem 51 KB -> 4 blocks/SM.
// ---------------------------------------------------------------------------
__global__ void __launch_bounds__(128) k_mix_kernel(
    const float* __restrict__ sig, float* __restrict__ out)
{
    extern __shared__ __align__(16) char smraw[];
    float* sS = (float*)smraw;                                   // [64][132] f32
    unsigned short* aHi = (unsigned short*)(smraw + 64 * SIG_PAD * 4);
    unsigned short* aLo = aHi + C_ * ATT_PAD;

    const int tid = threadIdx.x;
    const int b   = blockIdx.y;
    const int j0  = blockIdx.x * 128;

    // stage pre-split att (9216 B each, L2-hot)
    {
        const int4* gh = (const int4*)(g_att_hi + b * C_ * ATT_PAD);
        const int4* gl = (const int4*)(g_att_lo + b * C_ * ATT_PAD);
        int4* sh = (int4*)aHi;
        int4* sl = (int4*)aLo;
        #pragma unroll
        for (int i = tid; i < C_ * ATT_PAD / 8; i += 128) {
            sh[i] = gh[i];
            sl[i] = gl[i];
        }
    }

    // stage sig tile raw [64 i][128 j]
    {
        const float* sb = sig + (size_t)b * (C_ * NT_) + j0;
        #pragma unroll
        for (int idx = tid; idx < 64 * 32; idx += 128) {
            int row = idx >> 5, q = idx & 31;
            ((float4*)(sS + row * SIG_PAD))[q] =
                *(const float4*)(sb + (size_t)row * NT_ + q * 4);
        }
    }
    __syncthreads();

    const int lane = tid & 31;
    const int w    = tid >> 5;
    const int ctid = lane & 3;
    const int gid  = lane >> 2;

    float acc[4][4][4];
    #pragma unroll
    for (int m = 0; m < 4; m++)
        #pragma unroll
        for (int n = 0; n < 4; n++)
            acc[m][n][0] = acc[m][n][1] = acc[m][n][2] = acc[m][n][3] = 0.f;

    #pragma unroll
    for (int kstep = 0; kstep < 4; kstep++) {
        const int k0 = kstep * 16;

        // B fragments: 4 n-tiles, hi (PRMT-pack of truncations) + lo (residual)
        unsigned bh[4][2], bl[4][2];
        #pragma unroll
        for (int n = 0; n < 4; n++) {
            const float* col = sS + (w * 32 + n * 8 + gid);
            float f0 = col[(k0 + 2 * ctid)     * SIG_PAD];
            float f1 = col[(k0 + 2 * ctid + 1) * SIG_PAD];
            float f2 = col[(k0 + 2 * ctid + 8) * SIG_PAD];
            float f3 = col[(k0 + 2 * ctid + 9) * SIG_PAD];
            bh[n][0] = __byte_perm(__float_as_uint(f0), __float_as_uint(f1), 0x7632);
            bh[n][1] = __byte_perm(__float_as_uint(f2), __float_as_uint(f3), 0x7632);
            float l0 = f0 - __uint_as_float(__float_as_uint(f0) & 0xffff0000u);
            float l1 = f1 - __uint_as_float(__float_as_uint(f1) & 0xffff0000u);
            float l2 = f2 - __uint_as_float(__float_as_uint(f2) & 0xffff0000u);
            float l3 = f3 - __uint_as_float(__float_as_uint(f3) & 0xffff0000u);
            asm("cvt.rn.bf16x2.f32 %0, %1, %2;" : "=r"(bl[n][0]) : "f"(l1), "f"(l0));
            asm("cvt.rn.bf16x2.f32 %0, %1, %2;" : "=r"(bl[n][1]) : "f"(l3), "f"(l2));
        }

        #pragma unroll
        for (int m = 0; m < 4; m++) {
            const int c0 = m * 16 + gid;
            const int i0 = c0 * ATT_PAD + k0 + 2 * ctid;
            const int i1 = (c0 + 8) * ATT_PAD + k0 + 2 * ctid;
            unsigned ah0 = *(const unsigned*)(aHi + i0);
            unsigned ah1 = *(const unsigned*)(aHi + i1);
            unsigned ah2 = *(const unsigned*)(aHi + i0 + 8);
            unsigned ah3 = *(const unsigned*)(aHi + i1 + 8);
            unsigned al0 = *(const unsigned*)(aLo + i0);
            unsigned al1 = *(const unsigned*)(aLo + i1);
            unsigned al2 = *(const unsigned*)(aLo + i0 + 8);
            unsigned al3 = *(const unsigned*)(aLo + i1 + 8);
            #pragma unroll
            for (int n = 0; n < 4; n++) {
                MMA_BF16(acc[m][n][0], acc[m][n][1], acc[m][n][2], acc[m][n][3],
                         ah0, ah1, ah2, ah3, bh[n][0], bh[n][1]);
                MMA_BF16(acc[m][n][0], acc[m][n][1], acc[m][n][2], acc[m][n][3],
                         ah0, ah1, ah2, ah3, bl[n][0], bl[n][1]);
                MMA_BF16(acc[m][n][0], acc[m][n][1], acc[m][n][2], acc[m][n][3],
                         al0, al1, al2, al3, bh[n][0], bh[n][1]);
            }
        }
    }

    // epilogue: d0/d1 -> (c, j..j+1), d2/d3 -> (c+8, j..j+1)
    #pragma unroll
    for (int m = 0; m < 4; m++) {
        const int c = m * 16 + gid;
        #pragma unroll
        for (int n = 0; n < 4; n++) {
            const int j = j0 + w * 32 + n * 8 + ctid * 2;
            float* p0 = out + ((size_t)(b * C_ + c)) * NT_ + j;
            *(float2*)p0 = make_float2(acc[m][n][0], acc[m][n][1]);
            *(float2*)(p0 + (size_t)8 * NT_) = make_float2(acc[m][n][2], acc[m][n][3]);
        }
    }
}

// ---------------------------------------------------------------------------
extern "C" void kernel_launch(void* const* d_in, const int* in_sizes, int n_in,
                              void* d_out, int out_size)
{
    const float* sig   = (const float*)d_in[0];   // [16,64,512,128]
    const float* Wc    = (const float*)d_in[1];   // [128,128]
    const float* alpha = (const float*)d_in[2];   // [512]
    float* out = (float*)d_out;

    const int smem_mix = 64 * SIG_PAD * 4 + 2 * C_ * ATT_PAD * 2;  // 52224 B
    cudaFuncSetAttribute(k_mix_kernel,
                         cudaFuncAttributeMaxDynamicSharedMemorySize, smem_mix);

    k_reduce_kernel<<<B_ * C_, 256>>>(sig, alpha);
    k_att_kernel<<<B_ * 8, 256>>>(Wc);
    dim3 g3(NT_ / 128, B_);
    k_mix_kernel<<<g3, 128, smem_mix>>>(sig, out);
}